// round 1
// baseline (speedup 1.0000x reference)
#include <cuda_runtime.h>
#include <cuda_bf16.h>
#include <math.h>

// Problem constants
#define BV   32000
#define TT   2048
#define HH   4
#define NN_  4096
#define DD   256
#define LL   6
#define KK   1024     // N/H
#define BB   2
#define EPS  1e-5f

// ---------------- scratch (device globals; no mallocs allowed) ----------------
__device__ float g_v[BB*TT*DD];             // 4 MB
__device__ float g_x[BB*HH*TT*KK];          // 64 MB   [B,H,T,K]
__device__ float g_q[BB*HH*TT*KK];          // 64 MB
__device__ float g_scores[BB*HH*TT*TT];     // 128 MB  [B,H,T,T]
__device__ float g_a[BB*HH*TT*DD];          // 16 MB
__device__ float g_y[BB*TT*NN_];            // 32 MB   [B,T,N]
__device__ float g_yE[BB*TT*DD];            // 4 MB
__device__ float g_cos[TT*KK];              // 8 MB
__device__ float g_sin[TT*KK];              // 8 MB

// ---------------- block reduction (256 threads) ----------------
__device__ __forceinline__ float blockReduceSum256(float val) {
    __shared__ float s[8];
    __shared__ float res;
    int lane = threadIdx.x & 31, w = threadIdx.x >> 5;
    #pragma unroll
    for (int o = 16; o; o >>= 1) val += __shfl_xor_sync(0xffffffffu, val, o);
    if (lane == 0) s[w] = val;
    __syncthreads();
    if (threadIdx.x < 8) {
        float v = s[threadIdx.x];
        #pragma unroll
        for (int o = 4; o; o >>= 1) v += __shfl_xor_sync(0xffu, v, o);
        if (threadIdx.x == 0) res = v;
    }
    __syncthreads();
    float r = res;
    __syncthreads();   // protect res/s from next call's writes
    return r;
}

// ---------------- RoPE tables (fp32 pipeline matching jax) ----------------
__global__ void rope_table_kernel() {
    long idx = (long)blockIdx.x * blockDim.x + threadIdx.x;
    if (idx >= (long)TT * KK) return;
    int t = (int)(idx / KK);
    int k = (int)(idx % KK);
    int i = k & (KK / 2 - 1);
    float ex  = (2.0f * (float)i) / (float)KK;
    float inv = 1.0f / powf(10000.0f, ex);
    float th  = (float)t * inv;
    g_cos[idx] = cosf(th);
    g_sin[idx] = sinf(th);
}

// ---------------- embedding gather + LayerNorm ----------------
__global__ void embed_ln_kernel(const int* __restrict__ input_,
                                const float* __restrict__ emb) {
    int row = blockIdx.x;                 // B*T rows
    int tok = input_[row];
    float x = emb[(long)tok * DD + threadIdx.x];
    float mu = blockReduceSum256(x) * (1.0f / DD);
    float d = x - mu;
    float var = blockReduceSum256(d * d) * (1.0f / DD);
    g_v[(long)row * DD + threadIdx.x] = d * rsqrtf(var + EPS);
}

// ---------------- v += pos ----------------
__global__ void addpos_kernel(const float* __restrict__ pos) {
    long idx = (long)blockIdx.x * blockDim.x + threadIdx.x;   // B*T*D
    if (idx >= (long)BB * TT * DD) return;
    g_v[idx] += pos[idx % ((long)TT * DD)];
}

// ---------------- RoPE apply: q = x*cos + rot(x)*sin ----------------
__global__ void rope_apply_kernel() {
    long idx = (long)blockIdx.x * blockDim.x + threadIdx.x;  // B*H*T*K
    int k = (int)(idx & (KK - 1));
    int t = (int)((idx >> 10) & (TT - 1));
    float xv = g_x[idx];
    float other = (k < KK / 2) ? -g_x[idx + KK / 2] : g_x[idx - KK / 2];
    long tk = (long)t * KK + k;
    g_q[idx] = xv * g_cos[tk] + other * g_sin[tk];
}

// ---------------- generic row LayerNorm (in place), D=256 ----------------
__global__ void ln_rows_kernel(float* __restrict__ buf) {
    long row = blockIdx.x;
    float x = buf[row * DD + threadIdx.x];
    float mu = blockReduceSum256(x) * (1.0f / DD);
    float d = x - mu;
    float var = blockReduceSum256(d * d) * (1.0f / DD);
    buf[row * DD + threadIdx.x] = d * rsqrtf(var + EPS);
}

// ---------------- v = ln(v + ln(yE)) ----------------
__global__ void combine_kernel() {
    long row = blockIdx.x;                // B*T rows
    float u = g_yE[row * DD + threadIdx.x];
    float mu = blockReduceSum256(u) * (1.0f / DD);
    float d = u - mu;
    float var = blockReduceSum256(d * d) * (1.0f / DD);
    float w = g_v[row * DD + threadIdx.x] + d * rsqrtf(var + EPS);
    float mu2 = blockReduceSum256(w) * (1.0f / DD);
    float d2 = w - mu2;
    float var2 = blockReduceSum256(d2 * d2) * (1.0f / DD);
    g_v[row * DD + threadIdx.x] = d2 * rsqrtf(var2 + EPS);
}

// ---------------- tiled SGEMM ----------------
// C[M,N] = A[M,K] * op(B);  op(B)=B [K,N] (NN) or B^T with B stored [N,K] (NT)
// EPI: 0 = none, 1 = relu, 2 = relu then * Gate
// batching: z -> (b = z/Hdim, h = z%Hdim); per-operand (b,h) strides.
#define BM 128
#define BN 128
#define BKC 16
#define TM 8
#define TN 8

template<bool TRANSB, int EPI>
__global__ void __launch_bounds__(256, 2)
sgemm_kernel(const float* __restrict__ A, const float* __restrict__ B,
             float* __restrict__ C, const float* __restrict__ G,
             int M, int N, int Kd, int lda, int ldb, int ldc, int ldg,
             long sAb, long sAh, long sBb, long sBh,
             long sCb, long sCh, long sGb, long sGh, int Hdim)
{
    __shared__ float As[BKC][BM + 4];
    __shared__ float Bs[BKC][BN + 4];

    int z = blockIdx.z;
    int bb = z / Hdim, hh = z % Hdim;
    A += bb * sAb + hh * sAh;
    B += bb * sBb + hh * sBh;
    C += bb * sCb + hh * sCh;
    if (EPI == 2) G += bb * sGb + hh * sGh;

    int m0 = blockIdx.y * BM;
    int n0 = blockIdx.x * BN;
    int tid = threadIdx.x;
    int tx = tid & 15, ty = tid >> 4;

    float acc[TM][TN];
    #pragma unroll
    for (int i = 0; i < TM; i++)
        #pragma unroll
        for (int j = 0; j < TN; j++) acc[i][j] = 0.0f;

    for (int k0 = 0; k0 < Kd; k0 += BKC) {
        // load A tile (128 x 16), transpose into As[k][m]
        #pragma unroll
        for (int i = 0; i < 2; i++) {
            int p = tid + i * 256;
            int row = p >> 2;
            int c4  = (p & 3) * 4;
            float4 va = *reinterpret_cast<const float4*>(
                &A[(long)(m0 + row) * lda + k0 + c4]);
            As[c4 + 0][row] = va.x;
            As[c4 + 1][row] = va.y;
            As[c4 + 2][row] = va.z;
            As[c4 + 3][row] = va.w;
        }
        // load B tile
        if (!TRANSB) {
            #pragma unroll
            for (int i = 0; i < 2; i++) {
                int p = tid + i * 256;
                int row = p >> 5;
                int c4  = (p & 31) * 4;
                float4 vb = *reinterpret_cast<const float4*>(
                    &B[(long)(k0 + row) * ldb + n0 + c4]);
                *reinterpret_cast<float4*>(&Bs[row][c4]) = vb;
            }
        } else {
            #pragma unroll
            for (int i = 0; i < 2; i++) {
                int p = tid + i * 256;
                int nrow = p >> 2;
                int c4   = (p & 3) * 4;
                float4 vb = *reinterpret_cast<const float4*>(
                    &B[(long)(n0 + nrow) * ldb + k0 + c4]);
                Bs[c4 + 0][nrow] = vb.x;
                Bs[c4 + 1][nrow] = vb.y;
                Bs[c4 + 2][nrow] = vb.z;
                Bs[c4 + 3][nrow] = vb.w;
            }
        }
        __syncthreads();

        #pragma unroll
        for (int k = 0; k < BKC; k++) {
            float ra[TM], rb[TN];
            #pragma unroll
            for (int j = 0; j < TM; j++) ra[j] = As[k][ty * TM + j];
            #pragma unroll
            for (int j = 0; j < TN; j++) rb[j] = Bs[k][tx * TN + j];
            #pragma unroll
            for (int i = 0; i < TM; i++)
                #pragma unroll
                for (int j = 0; j < TN; j++)
                    acc[i][j] = fmaf(ra[i], rb[j], acc[i][j]);
        }
        __syncthreads();
    }

    // epilogue
    #pragma unroll
    for (int i = 0; i < TM; i++) {
        long cm = m0 + ty * TM + i;
        #pragma unroll
        for (int j = 0; j < TN; j += 4) {
            int cn = n0 + tx * TN + j;
            float4 r = make_float4(acc[i][j], acc[i][j+1], acc[i][j+2], acc[i][j+3]);
            if (EPI >= 1) {
                r.x = fmaxf(r.x, 0.f); r.y = fmaxf(r.y, 0.f);
                r.z = fmaxf(r.z, 0.f); r.w = fmaxf(r.w, 0.f);
            }
            if (EPI == 2) {
                float4 gv = *reinterpret_cast<const float4*>(&G[cm * ldg + cn]);
                r.x *= gv.x; r.y *= gv.y; r.z *= gv.z; r.w *= gv.w;
            }
            *reinterpret_cast<float4*>(&C[cm * (long)ldc + cn]) = r;
        }
    }
}

// ---------------- host launch ----------------
extern "C" void kernel_launch(void* const* d_in, const int* in_sizes, int n_in,
                              void* d_out, int out_size) {
    const int*   input_  = (const int*)d_in[0];
    const float* emb     = (const float*)d_in[1];
    const float* pos     = (const float*)d_in[2];
    const float* Dx      = (const float*)d_in[3];
    const float* Dy      = (const float*)d_in[4];
    const float* E       = (const float*)d_in[5];
    const float* readout = (const float*)d_in[6];
    float* out = (float*)d_out;

    float *v, *x, *q, *sc, *a, *y, *yE;
    cudaGetSymbolAddress((void**)&v,  g_v);
    cudaGetSymbolAddress((void**)&x,  g_x);
    cudaGetSymbolAddress((void**)&q,  g_q);
    cudaGetSymbolAddress((void**)&sc, g_scores);
    cudaGetSymbolAddress((void**)&a,  g_a);
    cudaGetSymbolAddress((void**)&y,  g_y);
    cudaGetSymbolAddress((void**)&yE, g_yE);

    const long TD = (long)TT * DD;      // 524288
    const long TK = (long)TT * KK;      // 2097152
    const long TTl = (long)TT * TT;     // 4194304
    const long TN_ = (long)TT * NN_;    // 8388608

    // RoPE tables (recomputed each call; deterministic)
    rope_table_kernel<<<(TT * KK + 255) / 256, 256>>>();

    // v = ln(emb[input])
    embed_ln_kernel<<<BB * TT, 256>>>(input_, emb);

    for (int l = 0; l < LL; l++) {
        // v += pos
        addpos_kernel<<<(BB * TT * DD + 255) / 256, 256>>>(pos);

        // x[b,h] = relu(v_b @ Dx_h) : M=2048 N=1024 K=256, z=8
        sgemm_kernel<false, 1><<<dim3(KK / BN, TT / BM, BB * HH), 256>>>(
            v, Dx, x, nullptr,
            TT, KK, DD, DD, KK, KK, 0,
            TD, 0, 0, (long)DD * KK, (long)HH * TK, TK, 0, 0, HH);

        // q = rope(x)
        rope_apply_kernel<<<(int)((long)BB * HH * TT * KK / 256), 256>>>();

        // scores[b,h] = q_bh @ q_bh^T : M=N=2048 K=1024
        sgemm_kernel<true, 0><<<dim3(TT / BN, TT / BM, BB * HH), 256>>>(
            q, q, sc, nullptr,
            TT, TT, KK, KK, KK, TT, 0,
            (long)HH * TK, TK, (long)HH * TK, TK, (long)HH * TTl, TTl, 0, 0, HH);

        // a[b,h] = scores_bh @ v_b : M=2048 N=256 K=2048
        sgemm_kernel<false, 0><<<dim3(DD / BN, TT / BM, BB * HH), 256>>>(
            sc, v, a, nullptr,
            TT, DD, TT, TT, DD, DD, 0,
            (long)HH * TTl, TTl, TD, 0, (long)HH * TD, TD, 0, 0, HH);

        // a = ln(a) row-wise
        ln_rows_kernel<<<BB * HH * TT, 256>>>(a);

        // y[b, t, h*K + k] = relu(ln(a)_bh @ Dy_h) * x[b,h,t,k]
        sgemm_kernel<false, 2><<<dim3(KK / BN, TT / BM, BB * HH), 256>>>(
            a, Dy, y, x,
            TT, KK, DD, DD, KK, NN_, KK,
            (long)HH * TD, TD, 0, (long)DD * KK,
            TN_, (long)KK, (long)HH * TK, TK, HH);

        // yE = y @ E : M = B*T = 4096, N=256, K=4096
        sgemm_kernel<false, 0><<<dim3(DD / BN, (BB * TT) / BM, 1), 256>>>(
            y, E, yE, nullptr,
            BB * TT, DD, NN_, NN_, DD, DD, 0,
            0, 0, 0, 0, 0, 0, 0, 0, 1);

        // v = ln(v + ln(yE))
        combine_kernel<<<BB * TT, 256>>>();
    }

    // out = v @ readout : M=4096 N=32000 K=256
    sgemm_kernel<false, 0><<<dim3(BV / BN, (BB * TT) / BM, 1), 256>>>(
        v, readout, out, nullptr,
        BB * TT, BV, DD, DD, BV, BV, 0,
        0, 0, 0, 0, 0, 0, 0, 0, 1);
}